// round 5
// baseline (speedup 1.0000x reference)
#include <cuda_runtime.h>

// Problem dims (fixed by the dataset)
#define TT 512
#define NN 64
#define DD 1024
#define HH 1024
#define GG 4096        // 4*H

#define NBLK 128       // persistent blocks, 1/SM (smem-bound), all co-resident

// Scratch (device globals: allocation-free per harness rules)
__device__ float g_xw[(size_t)TT * NN * GG];   // (T*N, 4H) precomputed x@Wx + b
__device__ float g_hbuf[2][NN * HH];           // double-buffered hidden state
__device__ unsigned g_count;                   // grid barrier counter
__device__ unsigned g_gen;                     // grid barrier generation

// dynamic smem layout (float2 units):
//   whs  [1024][16]  f2  : Wh slice, 16 col-pairs (32 cols), 128 KB
//   ash  [2][64][64] f2  : per-wg h chunk, duplicated {h,h}, 64 KB
//   pred [64][17]    f2  : preactivation exchange (aliases ash), padded
#define WHS_F2   (1024 * 16)
#define ASH_F2   (2 * 64 * 64)
#define SMEM_BYTES ((WHS_F2 + ASH_F2) * 8)     // 196608

// ---------------------------------------------------------------------------
// packed f32x2 helpers
// ---------------------------------------------------------------------------
__device__ __forceinline__ void fma2(float2& acc, const float2& a, const float2& b) {
    asm("fma.rn.f32x2 %0, %1, %2, %0;"
        : "+l"(reinterpret_cast<unsigned long long&>(acc))
        : "l"(reinterpret_cast<const unsigned long long&>(a)),
          "l"(reinterpret_cast<const unsigned long long&>(b)));
}
__device__ __forceinline__ unsigned long long dup2(float a) {
    unsigned long long r;
    asm("mov.b64 %0, {%1, %1};" : "=l"(r) : "f"(a));
    return r;
}
__device__ __forceinline__ float sigm(float x) { return 1.f / (1.f + __expf(-x)); }
__device__ __forceinline__ float tanh_(float x) { return 2.f / (1.f + __expf(-2.f * x)) - 1.f; }

// ---------------------------------------------------------------------------
// grid barrier: acquire/release, no nanosleep
// ---------------------------------------------------------------------------
__device__ __forceinline__ void grid_sync() {
    __syncthreads();
    if (threadIdx.x == 0) {
        unsigned my;
        asm volatile("ld.acquire.gpu.global.u32 %0, [%1];" : "=r"(my) : "l"(&g_gen));
        __threadfence();
        if (atomicAdd(&g_count, 1) == NBLK - 1) {
            atomicExch(&g_count, 0);
            asm volatile("st.release.gpu.global.u32 [%0], %1;" :: "l"(&g_gen), "r"(my + 1));
        } else {
            unsigned cur;
            do {
                asm volatile("ld.acquire.gpu.global.u32 %0, [%1];" : "=r"(cur) : "l"(&g_gen));
            } while (cur == my);
        }
    }
    __syncthreads();
}

// ---------------------------------------------------------------------------
// xW GEMM (unchanged from R4): g_xw[(t*64+n)*4096+g] = sum_d x[n][t][d]*Wx[d][g] + b[g]
// ---------------------------------------------------------------------------
__global__ __launch_bounds__(256) void xw_gemm(const float* __restrict__ x,
                                               const float* __restrict__ Wx,
                                               const float* __restrict__ b) {
    __shared__ float As[2][8][132];
    __shared__ float Bs[2][8][128];

    const int tid = threadIdx.x;
    const int ry = tid >> 4;
    const int cx = tid & 15;
    const int m0 = blockIdx.y * 128;
    const int nc0 = blockIdx.x * 128;

    float2 acc[8][4];
    #pragma unroll
    for (int i = 0; i < 8; i++)
        #pragma unroll
        for (int j = 0; j < 4; j++) acc[i][j] = make_float2(0.f, 0.f);

    const int r = tid >> 1;
    const int m = m0 + r;
    const float* arow = x + ((size_t)(m & 63) * TT + (size_t)(m >> 6)) * DD;
    const int kq = (tid & 1) * 4;
    const int kr = tid >> 5;
    const int cb = (tid & 31) * 4;
    const float* bsrc = Wx + (size_t)kr * GG + nc0 + cb;

    {
        float4 va = *(const float4*)(arow + kq);
        float4 vb = *(const float4*)bsrc;
        As[0][kq + 0][r] = va.x;
        As[0][kq + 1][r] = va.y;
        As[0][kq + 2][r] = va.z;
        As[0][kq + 3][r] = va.w;
        *(float4*)&Bs[0][kr][cb] = vb;
    }
    __syncthreads();

    for (int k0 = 0; k0 < DD; k0 += 8) {
        const int cur = (k0 >> 3) & 1;
        const bool more = (k0 + 8 < DD);
        float4 nva, nvb;
        if (more) {
            nva = *(const float4*)(arow + k0 + 8 + kq);
            nvb = *(const float4*)(bsrc + (size_t)(k0 + 8) * GG);
        }

        #pragma unroll
        for (int k = 0; k < 8; ++k) {
            float4 a0 = *(float4*)&As[cur][k][ry * 4];
            float4 a1 = *(float4*)&As[cur][k][64 + ry * 4];
            float2 A[8];
            ((unsigned long long*)A)[0] = dup2(a0.x);
            ((unsigned long long*)A)[1] = dup2(a0.y);
            ((unsigned long long*)A)[2] = dup2(a0.z);
            ((unsigned long long*)A)[3] = dup2(a0.w);
            ((unsigned long long*)A)[4] = dup2(a1.x);
            ((unsigned long long*)A)[5] = dup2(a1.y);
            ((unsigned long long*)A)[6] = dup2(a1.z);
            ((unsigned long long*)A)[7] = dup2(a1.w);
            float2 bb[4];
            *(float4*)&bb[0] = *(float4*)&Bs[cur][k][cx * 4];
            *(float4*)&bb[2] = *(float4*)&Bs[cur][k][64 + cx * 4];
            #pragma unroll
            for (int i = 0; i < 8; i++)
                #pragma unroll
                for (int j = 0; j < 4; j++) fma2(acc[i][j], A[i], bb[j]);
        }

        if (more) {
            const int nb = cur ^ 1;
            As[nb][kq + 0][r] = nva.x;
            As[nb][kq + 1][r] = nva.y;
            As[nb][kq + 2][r] = nva.z;
            As[nb][kq + 3][r] = nva.w;
            *(float4*)&Bs[nb][kr][cb] = nvb;
        }
        __syncthreads();
    }

    const int colj[4] = {cx * 4, cx * 4 + 2, 64 + cx * 4, 64 + cx * 4 + 2};
    float2 bias[4];
    #pragma unroll
    for (int j = 0; j < 4; j++) bias[j] = *(const float2*)&b[nc0 + colj[j]];

    #pragma unroll
    for (int i = 0; i < 8; i++) {
        int row = (i < 4) ? (ry * 4 + i) : (64 + ry * 4 + (i - 4));
        size_t base = (size_t)(m0 + row) * GG + nc0;
        #pragma unroll
        for (int j = 0; j < 4; j++) {
            float2 v = make_float2(acc[i][j].x + bias[j].x, acc[i][j].y + bias[j].y);
            *(float2*)&g_xw[base + colj[j]] = v;
        }
    }
}

// ---------------------------------------------------------------------------
// Persistent LSTM recurrence, gate-fused, single grid barrier per step.
// Block blk owns hidden strip j0 = blk*8; its 32 cols = 4 gates x 8 hidden.
// 256 threads = 2 warpgroups, K=1024 split 2 across wgs, smem-reduced.
// Wh slice (128 KB) resident in smem as col-pair float2.
// h chunk-staged duplicated {h,h} (8 chunks of 64 k).
// c and per-thread gate state live in registers for all 512 steps.
// ---------------------------------------------------------------------------
__global__ void __launch_bounds__(256, 1) lstm_persistent(
    const float* __restrict__ h0,
    const float* __restrict__ Wh,
    float* __restrict__ out) {
    extern __shared__ float2 sm2[];
    float2* whs = sm2;                 // [1024][16]
    float2* ash = sm2 + WHS_F2;        // [2][64][64]
    float2* pred = sm2 + WHS_F2;       // [64][17] (aliases ash; used post-k-loop)

    const int tid = threadIdx.x;
    const int blk = blockIdx.x;
    const int j0 = blk * 8;
    const int wg = tid >> 7;           // 0/1 -> K half
    const int t128 = tid & 127;

    // micro-tile coords (within wg): tile = 2 rows x 8 cols
    const int ry = t128 >> 2;          // 0..31 -> rows 2ry, 2ry+1
    const int cx = t128 & 3;           // 0..3  -> col-pairs 4cx..4cx+3 (gate cx)

    // stage coords
    const int s_row = t128 & 63;
    const int s_kh = t128 >> 6;        // 0/1

    // gate-phase coords: thread handles cells (g_row, j0+gp), (g_row, j0+gp+1)
    const int g_row = tid >> 2;        // 0..63
    const int gp = (tid & 3) * 2;      // 0,2,4,6

    // ---- load Wh slice into smem ONCE: whs[k][cp], cp -> cols {gc, gc+1} ----
    // cp = g*4 + p2h : gc = g*1024 + j0 + 2*p2h
    for (int idx = tid; idx < WHS_F2; idx += 256) {
        int k = idx >> 4;
        int cp = idx & 15;
        int gc = (cp >> 2) * HH + j0 + ((cp & 3) << 1);
        whs[idx] = *(const float2*)&Wh[(size_t)k * GG + gc];
    }

    // ---- init h buffer 0 and c ----
    {
        int e = (blk * 256 + tid) * 2;
        *(float2*)&g_hbuf[0][e] = *(const float2*)&h0[e];
    }
    float2 c = make_float2(0.f, 0.f);
    grid_sync();

    for (int t = 0; t < TT; ++t) {
        const int par = t & 1;
        const float* hcur = g_hbuf[par];

        // prefetch this thread's xw gate values (DRAM latency hidden by GEMM)
        float2 xg[4];
        {
            const float* xwt = g_xw + (size_t)t * NN * GG + (size_t)g_row * GG + j0 + gp;
            #pragma unroll
            for (int g = 0; g < 4; g++) xg[g] = *(const float2*)(xwt + g * HH);
        }

        // ---------- GEMM phase: preact = h @ Wh (this block's 32 cols) ----------
        float2 acc[2][4];
        #pragma unroll
        for (int r = 0; r < 2; r++)
            #pragma unroll
            for (int q = 0; q < 4; q++) acc[r][q] = make_float2(0.f, 0.f);

        const int kw0 = wg * 512;   // this wg's K base

        #pragma unroll 1
        for (int chunk = 0; chunk < 8; ++chunk) {
            __syncthreads();   // ash reuse safe
            // stage 64 k of h, duplicated
            {
                const int kb = kw0 + chunk * 64 + s_kh * 32;
                const float* src = hcur + (size_t)s_row * HH + kb;
                float2* dst = ash + wg * 4096 + (s_kh * 32) * 64 + s_row;
                #pragma unroll
                for (int i = 0; i < 8; ++i) {
                    float4 v = *(const float4*)(src + i * 4);
                    dst[(i * 4 + 0) * 64] = make_float2(v.x, v.x);
                    dst[(i * 4 + 1) * 64] = make_float2(v.y, v.y);
                    dst[(i * 4 + 2) * 64] = make_float2(v.z, v.z);
                    dst[(i * 4 + 3) * 64] = make_float2(v.w, v.w);
                }
            }
            __syncthreads();

            const float2* abase = ash + wg * 4096 + 2 * ry;
            const float2* bbase = whs + (size_t)(kw0 + chunk * 64) * 16 + 4 * cx;
            #pragma unroll 8
            for (int kc = 0; kc < 64; ++kc) {
                float2 A[2];
                *(float4*)A = *(const float4*)(abase + kc * 64);   // rows 2ry,2ry+1 dup'd
                float2 bb[4];
                *(float4*)&bb[0] = *(const float4*)(bbase + kc * 16);
                *(float4*)&bb[2] = *(const float4*)(bbase + kc * 16 + 2);
                #pragma unroll
                for (int r = 0; r < 2; r++)
                    #pragma unroll
                    for (int q = 0; q < 4; q++) fma2(acc[r][q], A[r], bb[q]);
            }
        }

        // ---------- reduce K halves via smem ----------
        __syncthreads();   // k-loop reads of ash done (pred aliases ash)
        if (wg == 1) {
            #pragma unroll
            for (int r = 0; r < 2; r++)
                #pragma unroll
                for (int q = 0; q < 4; q++)
                    pred[(2 * ry + r) * 17 + 4 * cx + q] = acc[r][q];
        }
        __syncthreads();
        if (wg == 0) {
            #pragma unroll
            for (int r = 0; r < 2; r++)
                #pragma unroll
                for (int q = 0; q < 4; q++) {
                    float2 v = pred[(2 * ry + r) * 17 + 4 * cx + q];
                    v.x += acc[r][q].x;
                    v.y += acc[r][q].y;
                    pred[(2 * ry + r) * 17 + 4 * cx + q] = v;
                }
        }
        __syncthreads();

        // ---------- gates (all 256 threads, 2 cells each) ----------
        {
            const int pc = gp >> 1;   // 0..3
            float2 pi = pred[g_row * 17 + 0 + pc];
            float2 pf = pred[g_row * 17 + 4 + pc];
            float2 po = pred[g_row * 17 + 8 + pc];
            float2 pg = pred[g_row * 17 + 12 + pc];
            pi.x += xg[0].x; pi.y += xg[0].y;
            pf.x += xg[1].x; pf.y += xg[1].y;
            po.x += xg[2].x; po.y += xg[2].y;
            pg.x += xg[3].x; pg.y += xg[3].y;

            float i0 = sigm(pi.x), f0 = sigm(pf.x), o0 = sigm(po.x), q0 = tanh_(pg.x);
            float i1 = sigm(pi.y), f1 = sigm(pf.y), o1 = sigm(po.y), q1 = tanh_(pg.y);
            c.x = f0 * c.x + i0 * q0;
            c.y = f1 * c.y + i1 * q1;
            float2 hv = make_float2(o0 * tanh_(c.x), o1 * tanh_(c.y));

            *(float2*)&g_hbuf[par ^ 1][g_row * HH + j0 + gp] = hv;
            *(float2*)&out[((size_t)g_row * TT + t) * HH + j0 + gp] = hv;
        }

        grid_sync();   // h(t) fully written before anyone stages step t+1
    }
}

// ---------------------------------------------------------------------------
// launch: exactly 2 kernel nodes in the graph
// ---------------------------------------------------------------------------
extern "C" void kernel_launch(void* const* d_in, const int* in_sizes, int n_in,
                              void* d_out, int out_size) {
    const float* x  = (const float*)d_in[0];   // (N,T,D)
    const float* h0 = (const float*)d_in[1];   // (N,H)
    const float* Wx = (const float*)d_in[2];   // (D,4H)
    const float* Wh = (const float*)d_in[3];   // (H,4H)
    const float* b  = (const float*)d_in[4];   // (4H,)
    float* out = (float*)d_out;                // (N,T,H)

    cudaFuncSetAttribute(lstm_persistent,
                         cudaFuncAttributeMaxDynamicSharedMemorySize, SMEM_BYTES);

    xw_gemm<<<dim3(GG / 128, (TT * NN) / 128), 256>>>(x, Wx, b);
    lstm_persistent<<<NBLK, 256, SMEM_BYTES>>>(h0, Wh, out);
}

// round 7
// speedup vs baseline: 1.9896x; 1.9896x over previous
#include <cuda_runtime.h>
#include <cuda_bf16.h>
#include <cstdint>

// Problem dims (fixed by the dataset)
#define TT 512
#define NN 64
#define DD 1024
#define HH 1024
#define GG 4096        // 4*H

#define NBLK 128       // persistent blocks for recurrence
#define KS 8           // K splits for recurrent GEMM
#define KC (HH / KS)   // 128
#define CGRP 16        // column groups
#define CW (GG / CGRP) // 256 cols per group
#define LSTM_SMEM (KC * CW * 4 + KC * 64 * 8)   // 196608

// ---- device scratch (allocation-free per harness rules) ----
__device__ float g_xw[(size_t)TT * NN * GG];        // (T*N, 4H) x@Wx + b
__device__ float g_part[KS][NN * GG];               // split-K partials of h@Wh
__device__ float g_h[NN * HH];                      // hidden state
__device__ unsigned g_count;
__device__ unsigned g_gen;

// bf16 hi/lo split operands for the xW tensor GEMM (k-contiguous rows)
__device__ __nv_bfloat16 g_xa_hi[(size_t)TT * NN * DD];   // A[m][k], m = t*64+n
__device__ __nv_bfloat16 g_xa_lo[(size_t)TT * NN * DD];
__device__ __nv_bfloat16 g_wxt_hi[(size_t)GG * DD];       // B[g][k] = Wx[k][g]
__device__ __nv_bfloat16 g_wxt_lo[(size_t)GG * DD];

// ---------------------------------------------------------------------------
// helpers
// ---------------------------------------------------------------------------
__device__ __forceinline__ void fma2(float2& acc, const float2& a, const float2& b) {
    asm("fma.rn.f32x2 %0, %1, %2, %0;"
        : "+l"(reinterpret_cast<unsigned long long&>(acc))
        : "l"(reinterpret_cast<const unsigned long long&>(a)),
          "l"(reinterpret_cast<const unsigned long long&>(b)));
}
__device__ __forceinline__ float sigm(float x) { return 1.f / (1.f + __expf(-x)); }
__device__ __forceinline__ float tanh_(float x) { return 2.f / (1.f + __expf(-2.f * x)) - 1.f; }

__device__ __forceinline__ void grid_sync() {
    __syncthreads();
    if (threadIdx.x == 0) {
        unsigned my;
        asm volatile("ld.acquire.gpu.global.u32 %0, [%1];" : "=r"(my) : "l"(&g_gen));
        __threadfence();
        if (atomicAdd(&g_count, 1) == NBLK - 1) {
            atomicExch(&g_count, 0);
            asm volatile("st.release.gpu.global.u32 [%0], %1;" :: "l"(&g_gen), "r"(my + 1));
        } else {
            unsigned cur;
            do {
                asm volatile("ld.acquire.gpu.global.u32 %0, [%1];" : "=r"(cur) : "l"(&g_gen));
            } while (cur == my);
        }
    }
    __syncthreads();
}

__device__ __forceinline__ uint32_t smem_u32(const void* p) {
    uint32_t a;
    asm("{ .reg .u64 t; cvta.to.shared.u64 t, %1; cvt.u32.u64 %0, t; }" : "=r"(a) : "l"(p));
    return a;
}

#define LDSM_X4(r0, r1, r2, r3, addr)                                           \
    asm volatile("ldmatrix.sync.aligned.m8n8.x4.shared.b16 {%0,%1,%2,%3}, [%4];" \
                 : "=r"(r0), "=r"(r1), "=r"(r2), "=r"(r3) : "r"(addr))

#define MMA_BF16(c, a0, a1, a2, a3, b0, b1)                                     \
    asm volatile("mma.sync.aligned.m16n8k16.row.col.f32.bf16.bf16.f32 "         \
                 "{%0,%1,%2,%3},{%4,%5,%6,%7},{%8,%9},{%0,%1,%2,%3};"           \
                 : "+f"(c[0]), "+f"(c[1]), "+f"(c[2]), "+f"(c[3])               \
                 : "r"(a0), "r"(a1), "r"(a2), "r"(a3), "r"(b0), "r"(b1))

// ---------------------------------------------------------------------------
// split kernels: fp32 -> bf16 hi + bf16 lo
// ---------------------------------------------------------------------------
__global__ __launch_bounds__(256) void split_x(const float* __restrict__ x) {
    const int m = blockIdx.x;               // m = t*64 + n
    const int t = m >> 6, n = m & 63;
    const float* src = x + ((size_t)n * TT + t) * DD;
    const int d0 = threadIdx.x * 4;
    float4 v = *(const float4*)(src + d0);
    float f[4] = {v.x, v.y, v.z, v.w};
    ushort4 hi, lo;
    unsigned short* hp = &hi.x;
    unsigned short* lp = &lo.x;
    #pragma unroll
    for (int i = 0; i < 4; i++) {
        __nv_bfloat16 h = __float2bfloat16(f[i]);
        __nv_bfloat16 l = __float2bfloat16(f[i] - __bfloat162float(h));
        hp[i] = __bfloat16_as_ushort(h);
        lp[i] = __bfloat16_as_ushort(l);
    }
    size_t o = (size_t)m * DD + d0;
    *(ushort4*)&g_xa_hi[o] = hi;
    *(ushort4*)&g_xa_lo[o] = lo;
}

__global__ __launch_bounds__(256) void split_wx(const float* __restrict__ Wx) {
    __shared__ float tile[32][33];
    const int g0 = blockIdx.x * 32, k0 = blockIdx.y * 32;
    const int tx = threadIdx.x & 31, ty = threadIdx.x >> 5;   // 32 x 8
    #pragma unroll
    for (int j = 0; j < 4; j++)
        tile[ty + j * 8][tx] = Wx[(size_t)(k0 + ty + j * 8) * GG + g0 + tx];
    __syncthreads();
    #pragma unroll
    for (int j = 0; j < 4; j++) {
        float v = tile[tx][ty + j * 8];
        __nv_bfloat16 h = __float2bfloat16(v);
        __nv_bfloat16 l = __float2bfloat16(v - __bfloat162float(h));
        size_t o = (size_t)(g0 + ty + j * 8) * DD + k0 + tx;
        g_wxt_hi[o] = h;
        g_wxt_lo[o] = l;
    }
}

// ---------------------------------------------------------------------------
// xW GEMM on tensor cores (mma.sync bf16, 3-term hi/lo split).
// D[m][g] = sum_k A[m][k]*B[g][k] + b[g];  tiles M=128, N=128, K step 32.
// 256 threads = 8 warps as 2(m) x 4(n); warp tile 64x32 = 4 m16 x 4 n8.
// smem rows stride 40 bf16 (80 B: 16B-aligned, ldmatrix conflict-free).
// ---------------------------------------------------------------------------
#define AST 40

__global__ __launch_bounds__(256) void xw_mma(const float* __restrict__ b) {
    __shared__ __nv_bfloat16 Ah[128 * AST], Al[128 * AST];
    __shared__ __nv_bfloat16 Bh[128 * AST], Bl[128 * AST];

    const int tid = threadIdx.x;
    const int wid = tid >> 5, lane = tid & 31;
    const int m0 = blockIdx.y * 128;
    const int g0 = blockIdx.x * 128;
    const int wm = (wid >> 2) * 64;      // warp m offset
    const int wn = (wid & 3) * 32;       // warp n offset

    float acc[4][4][4];
    #pragma unroll
    for (int i = 0; i < 4; i++)
        #pragma unroll
        for (int j = 0; j < 4; j++)
            #pragma unroll
            for (int q = 0; q < 4; q++) acc[i][j][q] = 0.f;

    // staging coords: thread -> (row, 32B half) ; 2 uint4 per array
    const int sr = tid >> 1;
    const int sh = (tid & 1) * 16;       // bf16 offset within 32-k row

    // ldmatrix smem addresses (lane-dependent parts precomputed)
    const uint32_t ah_b = smem_u32(Ah), al_b = smem_u32(Al);
    const uint32_t bh_b = smem_u32(Bh), bl_b = smem_u32(Bl);
    // A: row = wm + mt*16 + (lane&15), col = ks + ((lane>>4)<<3)
    const uint32_t a_off = (uint32_t)(wm + (lane & 15)) * (AST * 2) + ((lane >> 4) << 4);
    // B: row = wn + p*16 + ((lane>>4)<<3) + (lane&7), col = ks + (((lane>>3)&1)<<3)
    const uint32_t b_off = (uint32_t)(wn + ((lane >> 4) << 3) + (lane & 7)) * (AST * 2)
                           + (((lane >> 3) & 1) << 4);

    for (int k0 = 0; k0 < DD; k0 += 32) {
        // ---- stage: 128 rows x 32 k of Ahi/Alo/Bhi/Blo ----
        {
            const size_t ga = (size_t)(m0 + sr) * DD + k0 + sh;
            const size_t gb = (size_t)(g0 + sr) * DD + k0 + sh;
            const int so = sr * AST + sh;
            *(uint4*)&Ah[so]     = *(const uint4*)&g_xa_hi[ga];
            *(uint4*)&Ah[so + 8] = *(const uint4*)&g_xa_hi[ga + 8];
            *(uint4*)&Al[so]     = *(const uint4*)&g_xa_lo[ga];
            *(uint4*)&Al[so + 8] = *(const uint4*)&g_xa_lo[ga + 8];
            *(uint4*)&Bh[so]     = *(const uint4*)&g_wxt_hi[gb];
            *(uint4*)&Bh[so + 8] = *(const uint4*)&g_wxt_hi[gb + 8];
            *(uint4*)&Bl[so]     = *(const uint4*)&g_wxt_lo[gb];
            *(uint4*)&Bl[so + 8] = *(const uint4*)&g_wxt_lo[gb + 8];
        }
        __syncthreads();

        #pragma unroll
        for (int ks = 0; ks < 32; ks += 16) {
            const uint32_t kb = (uint32_t)ks * 2;
            // B fragments: p = 0,1 ; tiles nt = 2p (r0,r1) and 2p+1 (r2,r3)
            uint32_t bhf[4][2], blf[4][2];
            #pragma unroll
            for (int p = 0; p < 2; p++) {
                uint32_t r0, r1, r2, r3;
                uint32_t off = b_off + (uint32_t)(p * 16) * (AST * 2) + kb;
                LDSM_X4(r0, r1, r2, r3, bh_b + off);
                bhf[2 * p][0] = r0; bhf[2 * p][1] = r1;
                bhf[2 * p + 1][0] = r2; bhf[2 * p + 1][1] = r3;
                LDSM_X4(r0, r1, r2, r3, bl_b + off);
                blf[2 * p][0] = r0; blf[2 * p][1] = r1;
                blf[2 * p + 1][0] = r2; blf[2 * p + 1][1] = r3;
            }
            #pragma unroll
            for (int mt = 0; mt < 4; mt++) {
                uint32_t off = a_off + (uint32_t)(mt * 16) * (AST * 2) + kb;
                uint32_t ah0, ah1, ah2, ah3, al0, al1, al2, al3;
                LDSM_X4(ah0, ah1, ah2, ah3, ah_b + off);
                LDSM_X4(al0, al1, al2, al3, al_b + off);
                #pragma unroll
                for (int nt = 0; nt < 4; nt++) {
                    MMA_BF16(acc[mt][nt], ah0, ah1, ah2, ah3, bhf[nt][0], bhf[nt][1]);
                    MMA_BF16(acc[mt][nt], ah0, ah1, ah2, ah3, blf[nt][0], blf[nt][1]);
                    MMA_BF16(acc[mt][nt], al0, al1, al2, al3, bhf[nt][0], bhf[nt][1]);
                }
            }
        }
        __syncthreads();
    }

    // ---- epilogue: c0,c1 -> (row lane>>2, col 2(lane&3)); c2,c3 -> row+8 ----
    const int er = lane >> 2;
    const int ec = (lane & 3) * 2;
    #pragma unroll
    for (int mt = 0; mt < 4; mt++) {
        #pragma unroll
        for (int nt = 0; nt < 4; nt++) {
            const int col = g0 + wn + (nt >> 1) * 16 + (nt & 1) * 8 + ec;
            const float2 bias = *(const float2*)&b[col];
            const int row = m0 + wm + mt * 16 + er;
            float2 v0 = make_float2(acc[mt][nt][0] + bias.x, acc[mt][nt][1] + bias.y);
            float2 v1 = make_float2(acc[mt][nt][2] + bias.x, acc[mt][nt][3] + bias.y);
            *(float2*)&g_xw[(size_t)row * GG + col] = v0;
            *(float2*)&g_xw[(size_t)(row + 8) * GG + col] = v1;
        }
    }
}

// ---------------------------------------------------------------------------
// Persistent LSTM recurrence (proven R4 design + cheap barrier).
// Wh slice (128 KB) SMEM-resident; h chunk-staged pre-duplicated f32x2;
// split-K=8, col-groups=16, gates fused per thread; c in registers.
// ---------------------------------------------------------------------------
__global__ void __launch_bounds__(256, 1) lstm_persistent(
    const float* __restrict__ h0,
    const float* __restrict__ Wh,
    float* __restrict__ out) {
    extern __shared__ float smf[];
    float* Whs = smf;                                    // [KC][CW]
    float2* Ash = (float2*)(smf + KC * CW);              // [KC][64] dup {h,h}

    const int tid = threadIdx.x;
    const int blk = blockIdx.x;
    const int cg = blk >> 3;
    const int ks = blk & 7;
    const int nc0 = cg * CW;
    const int kbase = ks * KC;

    const int ge = (blk * 256 + tid) * 2;
    const int gn = ge >> 10;
    const int gj = ge & 1023;

    const int ry = tid >> 5;
    const int cx = tid & 31;

    {   // Wh slice -> smem once
        const int kk = tid >> 1;
        const int cb2 = (tid & 1) * 128;
        const float* src = Wh + (size_t)(kbase + kk) * GG + nc0 + cb2;
        float* dst = Whs + kk * CW + cb2;
        #pragma unroll
        for (int i = 0; i < 32; ++i)
            *(float4*)(dst + i * 4) = *(const float4*)(src + i * 4);
    }

    float2 c = make_float2(0.f, 0.f);
    *(float2*)&g_h[ge] = *(const float2*)&h0[ge];
    grid_sync();

    const int a_row = tid & 63;
    const int a_kq = (tid >> 6) * 32;
    const float* hsrc_base = g_h + (size_t)a_row * HH + kbase + a_kq;

    for (int t = 0; t < TT; ++t) {
        #pragma unroll
        for (int i = 0; i < 8; ++i) {
            float4 hv = *(const float4*)(hsrc_base + i * 4);
            const int k4 = a_kq + i * 4;
            Ash[(k4 + 0) * 64 + a_row] = make_float2(hv.x, hv.x);
            Ash[(k4 + 1) * 64 + a_row] = make_float2(hv.y, hv.y);
            Ash[(k4 + 2) * 64 + a_row] = make_float2(hv.z, hv.z);
            Ash[(k4 + 3) * 64 + a_row] = make_float2(hv.w, hv.w);
        }
        __syncthreads();

        float2 acc[8][4];
        #pragma unroll
        for (int i = 0; i < 8; i++)
            #pragma unroll
            for (int j = 0; j < 4; j++) acc[i][j] = make_float2(0.f, 0.f);

        #pragma unroll 8
        for (int kk = 0; kk < KC; ++kk) {
            const float2* ak = (const float2*)Ash + (size_t)kk * 64;
            float2 A[8];
            *(uint4*)&A[0] = *(const uint4*)(ak + 4 * ry);
            *(uint4*)&A[2] = *(const uint4*)(ak + 4 * ry + 2);
            *(uint4*)&A[4] = *(const uint4*)(ak + 32 + 4 * ry);
            *(uint4*)&A[6] = *(const uint4*)(ak + 32 + 4 * ry + 2);
            const float2* bk = (const float2*)Whs + (size_t)kk * 128;
            float2 bb[4] = {bk[cx], bk[cx + 32], bk[cx + 64], bk[cx + 96]};
            #pragma unroll
            for (int i = 0; i < 8; i++)
                #pragma unroll
                for (int j = 0; j < 4; j++) fma2(acc[i][j], A[i], bb[j]);
        }

        {
            float* dst = g_part[ks];
            #pragma unroll
            for (int i = 0; i < 8; i++) {
                int row = (i < 4) ? (4 * ry + i) : (32 + 4 * ry + (i - 4));
                size_t base = (size_t)row * GG + nc0;
                #pragma unroll
                for (int j = 0; j < 4; j++)
                    *(float2*)&dst[base + j * 64 + 2 * cx] = acc[i][j];
            }
        }
        grid_sync();

        {
            const float* xw = g_xw + (size_t)t * NN * GG;
            size_t bi = (size_t)gn * GG + gj;
            float2 pi = *(const float2*)&xw[bi];
            float2 pf = *(const float2*)&xw[bi + HH];
            float2 po = *(const float2*)&xw[bi + 2 * HH];
            float2 pg = *(const float2*)&xw[bi + 3 * HH];
            #pragma unroll
            for (int s = 0; s < KS; ++s) {
                const float* p = g_part[s];
                float2 v;
                v = *(const float2*)&p[bi];          pi.x += v.x; pi.y += v.y;
                v = *(const float2*)&p[bi + HH];     pf.x += v.x; pf.y += v.y;
                v = *(const float2*)&p[bi + 2 * HH]; po.x += v.x; po.y += v.y;
                v = *(const float2*)&p[bi + 3 * HH]; pg.x += v.x; pg.y += v.y;
            }
            float i0 = sigm(pi.x), f0 = sigm(pf.x), o0 = sigm(po.x), q0 = tanh_(pg.x);
            float i1 = sigm(pi.y), f1 = sigm(pf.y), o1 = sigm(po.y), q1 = tanh_(pg.y);
            c.x = f0 * c.x + i0 * q0;
            c.y = f1 * c.y + i1 * q1;
            float2 hv = make_float2(o0 * tanh_(c.x), o1 * tanh_(c.y));
            *(float2*)&g_h[ge] = hv;
            *(float2*)&out[((size_t)gn * TT + t) * HH + gj] = hv;
        }
        grid_sync();
    }
}

// ---------------------------------------------------------------------------
// launch
// ---------------------------------------------------------------------------
extern "C" void kernel_launch(void* const* d_in, const int* in_sizes, int n_in,
                              void* d_out, int out_size) {
    const float* x  = (const float*)d_in[0];
    const float* h0 = (const float*)d_in[1];
    const float* Wx = (const float*)d_in[2];
    const float* Wh = (const float*)d_in[3];
    const float* b  = (const float*)d_in[4];
    float* out = (float*)d_out;

    cudaFuncSetAttribute(lstm_persistent, cudaFuncAttributeMaxDynamicSharedMemorySize, LSTM_SMEM);

    split_x<<<TT * NN, 256>>>(x);
    split_wx<<<dim3(GG / 32, DD / 32), 256>>>(Wx);
    xw_mma<<<dim3(GG / 128, (TT * NN) / 128), 256>>>(b);
    lstm_persistent<<<NBLK, 256, LSTM_SMEM>>>(h0, Wh, out);
}